// round 1
// baseline (speedup 1.0000x reference)
#include <cuda_runtime.h>
#include <math.h>

#define Nn 50000
#define Ee 600000
#define Ff 16
#define Pp 32
#define Cc 128
#define Ll 6
#define BM 128
#define BK 32

// ---------------- scratch (static device globals; no allocation) -------------
__device__ float g_h[Nn * Cc];
__device__ float g_id[Nn * Cc];
__device__ float g_hw[Nn * Cc];
__device__ float g_agg[Nn * Cc];
__device__ int   g_cnt[Nn];
__device__ int   g_rowptr[Nn + 1];
__device__ int   g_pos[Nn];
__device__ int   g_srcs[Ee];
__device__ float g_ws[Ee];

// ---------------- input MLP: preproc + fc_in1 + fc_in2 ----------------------
__global__ __launch_bounds__(128) void k_input(
    const float* __restrict__ x,
    const float* __restrict__ Wp, const float* __restrict__ bp,
    const float* __restrict__ W1, const float* __restrict__ b1,
    const float* __restrict__ W2, const float* __restrict__ b2)
{
    __shared__ float sWp[Ff * Pp], sbp[Pp];
    __shared__ float sW1[Pp * Cc], sb1[Cc];
    __shared__ float sW2[Pp * Cc], sb2[Cc];
    __shared__ float xv[Ff], hp[Pp];
    int t = threadIdx.x;  // 128 threads
    for (int i = t; i < Ff * Pp; i += 128) sWp[i] = Wp[i];
    for (int i = t; i < Pp; i += 128)      sbp[i] = bp[i];
    for (int i = t; i < Pp * Cc; i += 128) { sW1[i] = W1[i]; sW2[i] = W2[i]; }
    sb1[t] = b1[t];
    sb2[t] = b2[t];
    __syncthreads();

    for (int n = blockIdx.x; n < Nn; n += gridDim.x) {
        if (t < Ff) xv[t] = x[n * Ff + t];
        __syncthreads();
        if (t < Pp) {
            float s = sbp[t];
            #pragma unroll
            for (int k = 0; k < Ff; k++) s += xv[k] * sWp[k * Pp + t];
            hp[t] = fmaxf(s, 0.f);
        }
        __syncthreads();
        float s1 = sb1[t], s2 = sb2[t];
        #pragma unroll
        for (int k = 0; k < Pp; k++) {
            float hk = hp[k];
            s1 += hk * sW1[k * Cc + t];
            s2 += hk * sW2[k * Cc + t];
        }
        g_id[(size_t)n * Cc + t] = fmaxf(s1, 0.f);
        g_h[(size_t)n * Cc + t]  = fmaxf(s2, 0.f);
        __syncthreads();  // protect xv/hp before next node
    }
}

// ---------------- generic fp32 GEMM: out = act(A@W + b), A = [A1 ; A2] ------
// A1 covers K rows [0,128), A2 covers [128,256). W row-major [K, 128].
// flags: bit0 = relu, bit1 = bias
__global__ __launch_bounds__(256) void k_gemm(
    const float* __restrict__ A1, const float* __restrict__ A2,
    const float* __restrict__ W, const float* __restrict__ bias,
    float* __restrict__ out, int K, int flags)
{
    __shared__ float As[BM][BK];
    __shared__ float Ws[BK][Cc];
    int tid = threadIdx.x;
    int tm = tid >> 5;        // 0..7 : row group of 16
    int tn = tid & 31;        // 0..31: col group of 4
    int row0 = blockIdx.x * BM;

    float4 acc[16];
    #pragma unroll
    for (int i = 0; i < 16; i++) acc[i] = make_float4(0.f, 0.f, 0.f, 0.f);

    int nkt = K / BK;
    for (int kt = 0; kt < nkt; kt++) {
        const float* A = (kt * BK < Cc) ? A1 : A2;
        int kbase = (kt * BK) & (Cc - 1);
        // load A tile 128x32 (float4 per thread x4), zero-pad OOB rows
        #pragma unroll
        for (int j = 0; j < 4; j++) {
            int i = tid + 256 * j;
            int r = i >> 3, k4 = (i & 7) * 4;
            float4 v = make_float4(0.f, 0.f, 0.f, 0.f);
            if (row0 + r < Nn)
                v = *(const float4*)&A[(size_t)(row0 + r) * Cc + kbase + k4];
            *(float4*)&As[r][k4] = v;
        }
        // load W tile 32x128
        #pragma unroll
        for (int j = 0; j < 4; j++) {
            int i = tid + 256 * j;
            int kk = i >> 5, c4 = (i & 31) * 4;
            *(float4*)&Ws[kk][c4] = *(const float4*)&W[(size_t)(kt * BK + kk) * Cc + c4];
        }
        __syncthreads();
        #pragma unroll 4
        for (int kk = 0; kk < BK; kk++) {
            float4 w = *(const float4*)&Ws[kk][tn * 4];
            #pragma unroll
            for (int i = 0; i < 16; i++) {
                float a = As[tm * 16 + i][kk];
                acc[i].x += a * w.x; acc[i].y += a * w.y;
                acc[i].z += a * w.z; acc[i].w += a * w.w;
            }
        }
        __syncthreads();
    }

    float4 b4 = make_float4(0.f, 0.f, 0.f, 0.f);
    if (flags & 2) b4 = *(const float4*)&bias[tn * 4];
    #pragma unroll
    for (int i = 0; i < 16; i++) {
        int r = row0 + tm * 16 + i;
        if (r < Nn) {
            float4 v = acc[i];
            v.x += b4.x; v.y += b4.y; v.z += b4.z; v.w += b4.w;
            if (flags & 1) {
                v.x = fmaxf(v.x, 0.f); v.y = fmaxf(v.y, 0.f);
                v.z = fmaxf(v.z, 0.f); v.w = fmaxf(v.w, 0.f);
            }
            *(float4*)&out[(size_t)r * Cc + tn * 4] = v;
        }
    }
}

// ---------------- CSR build ---------------------------------------------------
__global__ void k_zero_cnt() {
    for (int i = blockIdx.x * blockDim.x + threadIdx.x; i < Nn; i += gridDim.x * blockDim.x)
        g_cnt[i] = 0;
}
__global__ void k_hist(const int* __restrict__ dst) {
    for (int e = blockIdx.x * blockDim.x + threadIdx.x; e < Ee; e += gridDim.x * blockDim.x)
        atomicAdd(&g_cnt[dst[e]], 1);
}
__global__ __launch_bounds__(1024) void k_scan() {
    __shared__ int part[1024];
    int t = threadIdx.x;
    const int CH = (Nn + 1023) / 1024;  // 49
    int lo = t * CH, hi = min(lo + CH, Nn);
    int s = 0;
    for (int i = lo; i < hi; i++) s += g_cnt[i];
    part[t] = s;
    __syncthreads();
    for (int st = 1; st < 1024; st <<= 1) {
        int v = (t >= st) ? part[t - st] : 0;
        __syncthreads();
        part[t] += v;
        __syncthreads();
    }
    int run = (t == 0) ? 0 : part[t - 1];
    for (int i = lo; i < hi; i++) {
        g_rowptr[i] = run;
        g_pos[i] = run;
        run += g_cnt[i];
    }
    if (t == 0) g_rowptr[Nn] = Ee;
}
__global__ void k_scatter(const int* __restrict__ src, const int* __restrict__ dst,
                          const float* __restrict__ w) {
    for (int e = blockIdx.x * blockDim.x + threadIdx.x; e < Ee; e += gridDim.x * blockDim.x) {
        int d = dst[e];
        int p = atomicAdd(&g_pos[d], 1);
        g_srcs[p] = src[e];
        g_ws[p] = w[e];
    }
}

// ---------------- SpMM (segment sum) fused with bias+relu --------------------
__global__ __launch_bounds__(256) void k_spmm(const float* __restrict__ hw,
                                              const float* __restrict__ bias,
                                              float* __restrict__ out)
{
    int node = blockIdx.x * 8 + (threadIdx.x >> 5);
    int lane = threadIdx.x & 31;
    if (node >= Nn) return;
    int s = g_rowptr[node], e = g_rowptr[node + 1];
    float4 acc = make_float4(0.f, 0.f, 0.f, 0.f);
    for (int p = s; p < e; p += 32) {
        int src = 0; float w = 0.f;
        if (p + lane < e) { src = g_srcs[p + lane]; w = g_ws[p + lane]; }
        int cnt = min(32, e - p);
        for (int j = 0; j < cnt; j++) {
            int sj  = __shfl_sync(0xffffffffu, src, j);
            float wj = __shfl_sync(0xffffffffu, w, j);
            float4 v = *(const float4*)&hw[(size_t)sj * Cc + lane * 4];
            acc.x += v.x * wj; acc.y += v.y * wj;
            acc.z += v.z * wj; acc.w += v.w * wj;
        }
    }
    float4 b4 = *(const float4*)&bias[lane * 4];
    acc.x = fmaxf(acc.x + b4.x, 0.f);
    acc.y = fmaxf(acc.y + b4.y, 0.f);
    acc.z = fmaxf(acc.z + b4.z, 0.f);
    acc.w = fmaxf(acc.w + b4.w, 0.f);
    *(float4*)&out[(size_t)node * Cc + lane * 4] = acc;
}

// ---------------- final projection + sigmoid ---------------------------------
__global__ __launch_bounds__(256) void k_last2(const float* __restrict__ h,
                                               const float* __restrict__ W2,
                                               const float* __restrict__ b2,
                                               float* __restrict__ out)
{
    int node = blockIdx.x * 8 + (threadIdx.x >> 5);
    int lane = threadIdx.x & 31;
    if (node >= Nn) return;
    float4 v = *(const float4*)&h[(size_t)node * Cc + lane * 4];
    float hv[4] = {v.x, v.y, v.z, v.w};
    float s0 = 0.f, s1 = 0.f;
    #pragma unroll
    for (int q = 0; q < 4; q++) {
        int k = lane * 4 + q;
        s0 += hv[q] * W2[k * 2 + 0];
        s1 += hv[q] * W2[k * 2 + 1];
    }
    #pragma unroll
    for (int o = 16; o > 0; o >>= 1) {
        s0 += __shfl_xor_sync(0xffffffffu, s0, o);
        s1 += __shfl_xor_sync(0xffffffffu, s1, o);
    }
    if (lane == 0) {
        out[node * 2 + 0] = 1.f / (1.f + expf(-(s0 + b2[0])));
        out[node * 2 + 1] = 1.f / (1.f + expf(-(s1 + b2[1])));
    }
}

// ---------------- launch ------------------------------------------------------
extern "C" void kernel_launch(void* const* d_in, const int* in_sizes, int n_in,
                              void* d_out, int out_size)
{
    const float* x    = (const float*)d_in[0];
    const int*   esrc = (const int*)  d_in[1];
    const int*   edst = (const int*)  d_in[2];
    const float* ew   = (const float*)d_in[3];
    const float* pW   = (const float*)d_in[4];
    const float* pb   = (const float*)d_in[5];
    const float* W1   = (const float*)d_in[6];
    const float* b1   = (const float*)d_in[7];
    const float* W2i  = (const float*)d_in[8];
    const float* b2i  = (const float*)d_in[9];
    const float* gW   = (const float*)d_in[10];
    const float* gb   = (const float*)d_in[11];
    const float* fW   = (const float*)d_in[12];
    const float* fb   = (const float*)d_in[13];
    const float* l1W  = (const float*)d_in[14];
    const float* l1b  = (const float*)d_in[15];
    const float* l2W  = (const float*)d_in[16];
    const float* l2b  = (const float*)d_in[17];
    float* out = (float*)d_out;

    float *ph, *pid, *phw, *pagg;
    cudaGetSymbolAddress((void**)&ph,   g_h);
    cudaGetSymbolAddress((void**)&pid,  g_id);
    cudaGetSymbolAddress((void**)&phw,  g_hw);
    cudaGetSymbolAddress((void**)&pagg, g_agg);

    k_input<<<1024, 128>>>(x, pW, pb, W1, b1, W2i, b2i);

    k_zero_cnt<<<128, 256>>>();
    k_hist<<<512, 256>>>(edst);
    k_scan<<<1, 1024>>>();
    k_scatter<<<512, 256>>>(esrc, edst, ew);

    const int GB = (Nn + BM - 1) / BM;        // 391
    const int GS = (Nn + 7) / 8;              // 6250
    for (int l = 0; l < Ll; l++) {
        k_gemm<<<GB, 256>>>(ph, ph, gW + (size_t)l * Cc * Cc, (const float*)0, phw, Cc, 0);
        k_spmm<<<GS, 256>>>(phw, gb + (size_t)l * Cc, pagg);
        k_gemm<<<GB, 256>>>(pid, pagg, fW + (size_t)l * 2 * Cc * Cc, fb + (size_t)l * Cc, ph, 2 * Cc, 3);
    }
    k_gemm<<<GB, 256>>>(pid, ph, l1W, l1b, phw, 2 * Cc, 3);
    k_last2<<<GS, 256>>>(phw, l2W, l2b, out);
}

// round 5
// speedup vs baseline: 1.7726x; 1.7726x over previous
#include <cuda_runtime.h>
#include <cuda_bf16.h>
#include <stdint.h>
#include <math.h>

#define Nn 50000
#define Ee 600000
#define Ff 16
#define Pp 32
#define Cc 128
#define Ll 6

// ---------------- scratch (static device globals; no allocation) -------------
__device__ float g_h[Nn * Cc];
__device__ float g_id[Nn * Cc];
__device__ float g_hw[Nn * Cc];
__device__ float g_agg[Nn * Cc];
__device__ int   g_cnt[Nn];
__device__ int   g_rowptr[Nn + 1];
__device__ int   g_pos[Nn];
__device__ int   g_srcs[Ee];
__device__ float g_ws[Ee];
__device__ int   g_part[256];
// prepped (transposed, bf16 split) weights: layout [n][k] row-major per matrix
__device__ __align__(16) __nv_bfloat16 g_wg_hi[Ll * Cc * Cc];
__device__ __align__(16) __nv_bfloat16 g_wg_lo[Ll * Cc * Cc];
__device__ __align__(16) __nv_bfloat16 g_wf_hi[Ll * 2 * Cc * Cc];
__device__ __align__(16) __nv_bfloat16 g_wf_lo[Ll * 2 * Cc * Cc];
__device__ __align__(16) __nv_bfloat16 g_wl_hi[2 * Cc * Cc];
__device__ __align__(16) __nv_bfloat16 g_wl_lo[2 * Cc * Cc];

// ---------------- mma helpers -------------------------------------------------
__device__ __forceinline__ uint32_t smem_u32(const void* p) {
    uint32_t a;
    asm("{ .reg .u64 t; cvta.to.shared.u64 t, %1; cvt.u32.u64 %0, t; }" : "=r"(a) : "l"(p));
    return a;
}
__device__ __forceinline__ void ldsm4(uint32_t* r, uint32_t a) {
    asm volatile("ldmatrix.sync.aligned.m8n8.x4.shared.b16 {%0,%1,%2,%3}, [%4];"
        : "=r"(r[0]), "=r"(r[1]), "=r"(r[2]), "=r"(r[3]) : "r"(a));
}
__device__ __forceinline__ void ldsm2(uint32_t* r, uint32_t a) {
    asm volatile("ldmatrix.sync.aligned.m8n8.x2.shared.b16 {%0,%1}, [%2];"
        : "=r"(r[0]), "=r"(r[1]) : "r"(a));
}
__device__ __forceinline__ void mma16816(float* d, const uint32_t* a, const uint32_t* b) {
    asm volatile("mma.sync.aligned.m16n8k16.row.col.f32.bf16.bf16.f32 "
        "{%0,%1,%2,%3}, {%4,%5,%6,%7}, {%8,%9}, {%0,%1,%2,%3};"
        : "+f"(d[0]), "+f"(d[1]), "+f"(d[2]), "+f"(d[3])
        : "r"(a[0]), "r"(a[1]), "r"(a[2]), "r"(a[3]), "r"(b[0]), "r"(b[1]));
}

// ---------------- input MLP: preproc + fc_in1 + fc_in2 ----------------------
__global__ __launch_bounds__(128) void k_input(
    const float* __restrict__ x,
    const float* __restrict__ Wp, const float* __restrict__ bp,
    const float* __restrict__ W1, const float* __restrict__ b1,
    const float* __restrict__ W2, const float* __restrict__ b2)
{
    __shared__ float sWp[Ff * Pp], sbp[Pp];
    __shared__ float sW1[Pp * Cc], sb1[Cc];
    __shared__ float sW2[Pp * Cc], sb2[Cc];
    __shared__ float xv[Ff], hp[Pp];
    int t = threadIdx.x;
    for (int i = t; i < Ff * Pp; i += 128) sWp[i] = Wp[i];
    for (int i = t; i < Pp; i += 128)      sbp[i] = bp[i];
    for (int i = t; i < Pp * Cc; i += 128) { sW1[i] = W1[i]; sW2[i] = W2[i]; }
    sb1[t] = b1[t];
    sb2[t] = b2[t];
    __syncthreads();

    for (int n = blockIdx.x; n < Nn; n += gridDim.x) {
        if (t < Ff) xv[t] = x[n * Ff + t];
        __syncthreads();
        if (t < Pp) {
            float s = sbp[t];
            #pragma unroll
            for (int k = 0; k < Ff; k++) s += xv[k] * sWp[k * Pp + t];
            hp[t] = fmaxf(s, 0.f);
        }
        __syncthreads();
        float s1 = sb1[t], s2 = sb2[t];
        #pragma unroll
        for (int k = 0; k < Pp; k++) {
            float hk = hp[k];
            s1 += hk * sW1[k * Cc + t];
            s2 += hk * sW2[k * Cc + t];
        }
        g_id[(size_t)n * Cc + t] = fmaxf(s1, 0.f);
        g_h[(size_t)n * Cc + t]  = fmaxf(s2, 0.f);
        __syncthreads();
    }
}

// ---------------- weight prep: transpose + bf16 split -------------------------
__global__ void k_prepw(const float* __restrict__ gW, const float* __restrict__ fW,
                        const float* __restrict__ l1W)
{
    int idx = blockIdx.x * 256 + threadIdx.x;  // 0 .. 327679
    float v;
    __nv_bfloat16 *hi, *lo;
    size_t o;
    if (idx < Ll * Cc * Cc) {
        int l = idx >> 14, r = idx & 16383;
        int n = r >> 7, k = r & 127;
        v = gW[(size_t)l * 16384 + (size_t)k * 128 + n];
        o = (size_t)l * 16384 + (size_t)n * 128 + k;
        hi = g_wg_hi; lo = g_wg_lo;
    } else if (idx < Ll * Cc * Cc + Ll * 2 * Cc * Cc) {
        int j = idx - Ll * Cc * Cc;
        int l = j >> 15, r = j & 32767;
        int n = r >> 8, k = r & 255;
        v = fW[(size_t)l * 32768 + (size_t)k * 128 + n];
        o = (size_t)l * 32768 + (size_t)n * 256 + k;
        hi = g_wf_hi; lo = g_wf_lo;
    } else {
        int j = idx - (Ll * Cc * Cc + Ll * 2 * Cc * Cc);
        int n = j >> 8, k = j & 255;
        v = l1W[(size_t)k * 128 + n];
        o = (size_t)n * 256 + k;
        hi = g_wl_hi; lo = g_wl_lo;
    }
    __nv_bfloat16 h = __float2bfloat16(v);
    hi[o] = h;
    lo[o] = __float2bfloat16(v - __bfloat162float(h));
}

// ---------------- HMMA GEMM: out = act(A@W + b) ------------------------------
// A = [A1 ; A2] fp32 (each 128 k-cols). W prepped bf16 [n][K]. flags: 1=relu, 2=bias
// CTA: 128 rows x 128 cols, 512 threads = 16 warps (4 m-groups x 4 n-groups),
// warp tile 32x32 = 2 m-tiles(16) x 4 n-tiles(8). K chunked by 64 through smem.
#define PADK 72                      // 64 + 8 bf16 pad
#define TILE_B (128 * PADK * 2)      // 18432 bytes per tile
#define TG_SMEM (4 * TILE_B)         // Wh, Wl, Ah, Al
__global__ __launch_bounds__(512) void k_tgemm(
    const float* __restrict__ A1, const float* __restrict__ A2,
    const __nv_bfloat16* __restrict__ Wh, const __nv_bfloat16* __restrict__ Wl,
    const float* __restrict__ bias, float* __restrict__ out, int K, int flags)
{
    extern __shared__ char sm[];
    char* sWh = sm;
    char* sAh = sm + 2 * TILE_B;
    uint32_t uWh = smem_u32(sWh);
    uint32_t uAh = smem_u32(sAh);

    int tid = threadIdx.x;
    int wid = tid >> 5, lane = tid & 31;
    int wm = wid & 3, wn = wid >> 2;           // 4 x 4 warp grid
    int rim = lane & 7, mid = lane >> 3;
    int row0 = blockIdx.x * 128;

    float acc[2][4][4];
    #pragma unroll
    for (int mt = 0; mt < 2; mt++)
        #pragma unroll
        for (int nt = 0; nt < 4; nt++)
            #pragma unroll
            for (int q = 0; q < 4; q++) acc[mt][nt][q] = 0.f;

    // per-thread ldmatrix base addresses (byte offsets at k-step 0)
    uint32_t aAddr[2], bAddr[4];
    #pragma unroll
    for (int mt = 0; mt < 2; mt++) {
        int r = wm * 32 + mt * 16 + rim + (mid & 1) * 8;
        int c = (mid >> 1) * 8;
        aAddr[mt] = uAh + (uint32_t)((r * PADK + c) << 1);
    }
    #pragma unroll
    for (int nt = 0; nt < 4; nt++) {
        int r = wn * 32 + nt * 8 + rim;
        int c = (mid & 1) * 8;
        bAddr[nt] = uWh + (uint32_t)((r * PADK + c) << 1);
    }

    int nch = K >> 6;
    for (int ch = 0; ch < nch; ch++) {
        if (ch) __syncthreads();
        const float* A = (ch * 64 < Cc) ? A1 : A2;
        int kA = (ch * 64) & (Cc - 1);
        // ---- A chunk: 128 rows x 64 fp32 -> bf16 hi/lo (2048 float4 slots) ----
        #pragma unroll
        for (int j = 0; j < 4; j++) {
            int i = tid + 512 * j;
            int r = i >> 4, c = (i & 15) * 4;
            float4 v = make_float4(0.f, 0.f, 0.f, 0.f);
            if (row0 + r < Nn)
                v = *(const float4*)(A + (size_t)(row0 + r) * Cc + kA + c);
            __nv_bfloat162 h01 = __floats2bfloat162_rn(v.x, v.y);
            __nv_bfloat162 h23 = __floats2bfloat162_rn(v.z, v.w);
            __nv_bfloat162 l01 = __floats2bfloat162_rn(v.x - __bfloat162float(h01.x),
                                                       v.y - __bfloat162float(h01.y));
            __nv_bfloat162 l23 = __floats2bfloat162_rn(v.z - __bfloat162float(h23.x),
                                                       v.w - __bfloat162float(h23.y));
            uint32_t off = (uint32_t)((r * PADK + c) << 1);
            *(__nv_bfloat162*)(sAh + off)              = h01;
            *(__nv_bfloat162*)(sAh + off + 4)          = h23;
            *(__nv_bfloat162*)(sAh + TILE_B + off)     = l01;
            *(__nv_bfloat162*)(sAh + TILE_B + off + 4) = l23;
        }
        // ---- W chunk: 128 n-rows x 64 k bf16 = 1024 uint4 slots (j < 2!) ----
        int kW = ch * 64;
        #pragma unroll
        for (int j = 0; j < 2; j++) {
            int i = tid + 512 * j;
            int n = i >> 3, k8 = (i & 7) * 8;
            uint4 vh = *(const uint4*)(Wh + (size_t)n * K + kW + k8);
            uint4 vl = *(const uint4*)(Wl + (size_t)n * K + kW + k8);
            uint32_t off = (uint32_t)((n * PADK + k8) << 1);
            *(uint4*)(sWh + off)          = vh;
            *(uint4*)(sWh + TILE_B + off) = vl;
        }
        __syncthreads();

        #pragma unroll
        for (int ks = 0; ks < 4; ks++) {
            uint32_t ka = ks * 32;  // 16 bf16 = 32 bytes
            uint32_t ah[2][4], al[2][4];
            ldsm4(ah[0], aAddr[0] + ka);
            ldsm4(ah[1], aAddr[1] + ka);
            ldsm4(al[0], aAddr[0] + ka + TILE_B);
            ldsm4(al[1], aAddr[1] + ka + TILE_B);
            #pragma unroll
            for (int nt = 0; nt < 4; nt++) {
                uint32_t bh[2], bl[2];
                ldsm2(bh, bAddr[nt] + ka);
                ldsm2(bl, bAddr[nt] + ka + TILE_B);
                mma16816(acc[0][nt], ah[0], bh);
                mma16816(acc[0][nt], ah[0], bl);
                mma16816(acc[0][nt], al[0], bh);
                mma16816(acc[1][nt], ah[1], bh);
                mma16816(acc[1][nt], ah[1], bl);
                mma16816(acc[1][nt], al[1], bh);
            }
        }
    }

    // ---- epilogue ----
    int gr = row0 + wm * 32 + (lane >> 2);
    int gc = wn * 32 + (lane & 3) * 2;
    #pragma unroll
    for (int nt = 0; nt < 4; nt++) {
        int col = gc + nt * 8;
        float2 b2 = make_float2(0.f, 0.f);
        if (flags & 2) b2 = *(const float2*)(bias + col);
        #pragma unroll
        for (int mt = 0; mt < 2; mt++) {
            #pragma unroll
            for (int half = 0; half < 2; half++) {
                int r = gr + mt * 16 + half * 8;
                if (r < Nn) {
                    float v0 = acc[mt][nt][2 * half + 0] + b2.x;
                    float v1 = acc[mt][nt][2 * half + 1] + b2.y;
                    if (flags & 1) { v0 = fmaxf(v0, 0.f); v1 = fmaxf(v1, 0.f); }
                    *(float2*)(out + (size_t)r * Cc + col) = make_float2(v0, v1);
                }
            }
        }
    }
}

// ---------------- CSR build ---------------------------------------------------
__global__ void k_zero_cnt() {
    for (int i = blockIdx.x * blockDim.x + threadIdx.x; i < Nn; i += gridDim.x * blockDim.x)
        g_cnt[i] = 0;
}
__global__ void k_hist(const int* __restrict__ dst) {
    for (int e = blockIdx.x * blockDim.x + threadIdx.x; e < Ee; e += gridDim.x * blockDim.x)
        atomicAdd(&g_cnt[dst[e]], 1);
}
#define SCHUNK 196
__global__ __launch_bounds__(256) void k_scan1() {
    __shared__ int s[256];
    int t = threadIdx.x, b = blockIdx.x;
    int i = b * SCHUNK + t;
    int v = (t < SCHUNK && i < Nn) ? g_cnt[i] : 0;
    s[t] = v; __syncthreads();
    for (int st = 128; st > 0; st >>= 1) {
        if (t < st) s[t] += s[t + st];
        __syncthreads();
    }
    if (t == 0) g_part[b] = s[0];
}
__global__ __launch_bounds__(256) void k_scan2() {
    __shared__ int s[256];
    int t = threadIdx.x;
    int v = g_part[t];
    s[t] = v; __syncthreads();
    for (int st = 1; st < 256; st <<= 1) {
        int x = (t >= st) ? s[t - st] : 0;
        __syncthreads();
        s[t] += x;
        __syncthreads();
    }
    g_part[t] = s[t] - v;  // exclusive
}
__global__ __launch_bounds__(256) void k_scan3() {
    __shared__ int s[256];
    int t = threadIdx.x, b = blockIdx.x;
    int i = b * SCHUNK + t;
    int valid = (t < SCHUNK && i < Nn);
    int v = valid ? g_cnt[i] : 0;
    s[t] = v; __syncthreads();
    for (int st = 1; st < 256; st <<= 1) {
        int x = (t >= st) ? s[t - st] : 0;
        __syncthreads();
        s[t] += x;
        __syncthreads();
    }
    if (valid) {
        int rp = g_part[b] + s[t] - v;
        g_rowptr[i] = rp;
        g_pos[i] = rp;
    }
    if (b == 0 && t == 0) g_rowptr[Nn] = Ee;
}
__global__ void k_scatter(const int* __restrict__ src, const int* __restrict__ dst,
                          const float* __restrict__ w) {
    for (int e = blockIdx.x * blockDim.x + threadIdx.x; e < Ee; e += gridDim.x * blockDim.x) {
        int d = dst[e];
        int p = atomicAdd(&g_pos[d], 1);
        g_srcs[p] = src[e];
        g_ws[p] = w[e];
    }
}

// ---------------- SpMM (segment sum) fused with bias+relu --------------------
__global__ __launch_bounds__(256) void k_spmm(const float* __restrict__ hw,
                                              const float* __restrict__ bias,
                                              float* __restrict__ out)
{
    int node = blockIdx.x * 8 + (threadIdx.x >> 5);
    int lane = threadIdx.x & 31;
    if (node >= Nn) return;
    int s = g_rowptr[node], e = g_rowptr[node + 1];
    float4 acc = make_float4(0.f, 0.f, 0.f, 0.f);
    for (int p = s; p < e; p += 32) {
        int src = 0; float w = 0.f;
        if (p + lane < e) { src = g_srcs[p + lane]; w = g_ws[p + lane]; }
        int cnt = min(32, e - p);
        for (int j = 0; j < cnt; j++) {
            int sj  = __shfl_sync(0xffffffffu, src, j);
            float wj = __shfl_sync(0xffffffffu, w, j);
            float4 v = *(const float4*)&hw[(size_t)sj * Cc + lane * 4];
            acc.x += v.x * wj; acc.y += v.y * wj;
            acc.z += v.z * wj; acc.w += v.w * wj;
        }
    }
    float4 b4 = *(const float4*)&bias[lane * 4];
    acc.x = fmaxf(acc.x + b4.x, 0.f);
    acc.y = fmaxf(acc.y + b4.y, 0.f);
    acc.z = fmaxf(acc.z + b4.z, 0.f);
    acc.w = fmaxf(acc.w + b4.w, 0.f);
    *(float4*)&out[(size_t)node * Cc + lane * 4] = acc;
}

// ---------------- final projection + sigmoid ---------------------------------
__global__ __launch_bounds__(256) void k_last2(const float* __restrict__ h,
                                               const float* __restrict__ W2,
                                               const float* __restrict__ b2,
                                               float* __restrict__ out)
{
    int node = blockIdx.x * 8 + (threadIdx.x >> 5);
    int lane = threadIdx.x & 31;
    if (node >= Nn) return;
    float4 v = *(const float4*)&h[(size_t)node * Cc + lane * 4];
    float hv[4] = {v.x, v.y, v.z, v.w};
    float s0 = 0.f, s1 = 0.f;
    #pragma unroll
    for (int q = 0; q < 4; q++) {
        int k = lane * 4 + q;
        s0 += hv[q] * W2[k * 2 + 0];
        s1 += hv[q] * W2[k * 2 + 1];
    }
    #pragma unroll
    for (int o = 16; o > 0; o >>= 1) {
        s0 += __shfl_xor_sync(0xffffffffu, s0, o);
        s1 += __shfl_xor_sync(0xffffffffu, s1, o);
    }
    if (lane == 0) {
        out[node * 2 + 0] = 1.f / (1.f + expf(-(s0 + b2[0])));
        out[node * 2 + 1] = 1.f / (1.f + expf(-(s1 + b2[1])));
    }
}

// ---------------- launch ------------------------------------------------------
extern "C" void kernel_launch(void* const* d_in, const int* in_sizes, int n_in,
                              void* d_out, int out_size)
{
    const float* x    = (const float*)d_in[0];
    const int*   esrc = (const int*)  d_in[1];
    const int*   edst = (const int*)  d_in[2];
    const float* ew   = (const float*)d_in[3];
    const float* pW   = (const float*)d_in[4];
    const float* pb   = (const float*)d_in[5];
    const float* W1   = (const float*)d_in[6];
    const float* b1   = (const float*)d_in[7];
    const float* W2i  = (const float*)d_in[8];
    const float* b2i  = (const float*)d_in[9];
    const float* gW   = (const float*)d_in[10];
    const float* gb   = (const float*)d_in[11];
    const float* fW   = (const float*)d_in[12];
    const float* fb   = (const float*)d_in[13];
    const float* l1W  = (const float*)d_in[14];
    const float* l1b  = (const float*)d_in[15];
    const float* l2W  = (const float*)d_in[16];
    const float* l2b  = (const float*)d_in[17];
    float* out = (float*)d_out;

    cudaFuncSetAttribute(k_tgemm, cudaFuncAttributeMaxDynamicSharedMemorySize, TG_SMEM);

    float *ph, *pid, *phw, *pagg;
    cudaGetSymbolAddress((void**)&ph,   g_h);
    cudaGetSymbolAddress((void**)&pid,  g_id);
    cudaGetSymbolAddress((void**)&phw,  g_hw);
    cudaGetSymbolAddress((void**)&pagg, g_agg);
    __nv_bfloat16 *pwgh, *pwgl, *pwfh, *pwfl, *pwlh, *pwll;
    cudaGetSymbolAddress((void**)&pwgh, g_wg_hi);
    cudaGetSymbolAddress((void**)&pwgl, g_wg_lo);
    cudaGetSymbolAddress((void**)&pwfh, g_wf_hi);
    cudaGetSymbolAddress((void**)&pwfl, g_wf_lo);
    cudaGetSymbolAddress((void**)&pwlh, g_wl_hi);
    cudaGetSymbolAddress((void**)&pwll, g_wl_lo);

    k_input<<<1024, 128>>>(x, pW, pb, W1, b1, W2i, b2i);
    k_prepw<<<1280, 256>>>(gW, fW, l1W);

    k_zero_cnt<<<128, 256>>>();
    k_hist<<<512, 256>>>(edst);
    k_scan1<<<256, 256>>>();
    k_scan2<<<1, 256>>>();
    k_scan3<<<256, 256>>>();
    k_scatter<<<512, 256>>>(esrc, edst, ew);

    const int GB = (Nn + 127) / 128;   // 391
    const int GS = (Nn + 7) / 8;       // 6250
    for (int l = 0; l < Ll; l++) {
        k_tgemm<<<GB, 512, TG_SMEM>>>(ph, ph,
            pwgh + (size_t)l * Cc * Cc, pwgl + (size_t)l * Cc * Cc,
            (const float*)0, phw, Cc, 0);
        k_spmm<<<GS, 256>>>(phw, gb + (size_t)l * Cc, pagg);
        k_tgemm<<<GB, 512, TG_SMEM>>>(pid, pagg,
            pwfh + (size_t)l * 2 * Cc * Cc, pwfl + (size_t)l * 2 * Cc * Cc,
            fb + (size_t)l * Cc, ph, 2 * Cc, 3);
    }
    k_tgemm<<<GB, 512, TG_SMEM>>>(pid, ph, pwlh, pwll, l1b, phw, 2 * Cc, 3);
    k_last2<<<GS, 256>>>(phw, l2W, l2b, out);
}